// round 15
// baseline (speedup 1.0000x reference)
#include <cuda_runtime.h>
#include <math.h>

#define BB   8
#define NSEQ 512
#define DMODEL 512
#define HH   8
#define DHD  64
#define NPOS 121
#define EPSF 1e-7f

typedef unsigned long long ull;

// ---------------- scratch ----------------
__device__ float g_q [BB*HH*NSEQ*DHD];
__device__ float g_k [BB*HH*NSEQ*DHD];
__device__ float g_v [BB*HH*NSEQ*DHD];
__device__ float g_qp[BB*HH*NSEQ*128];
__device__ float g_maps[(size_t)BB*HH*NSEQ*NSEQ];
__device__ float g_y1  [(size_t)BB*16*NSEQ*NSEQ];
__device__ float g_part[128*256*2];
__device__ float g_nrm [128*2];
__device__ float g_ctx [BB*NSEQ*DMODEL];
__device__ float g_tmp [BB*NSEQ*DMODEL];

// ---------------- f32x2 helpers ----------------
__device__ __forceinline__ ull pk2(float a, float b){
    ull r; asm("mov.b64 %0, {%1,%2};" : "=l"(r) : "f"(a), "f"(b)); return r;
}
__device__ __forceinline__ void upk2(ull v, float& a, float& b){
    asm("mov.b64 {%0,%1}, %2;" : "=f"(a), "=f"(b) : "l"(v));
}
__device__ __forceinline__ void fma2(ull& d, ull a, ull b){
    asm("fma.rn.f32x2 %0, %1, %2, %3;" : "=l"(d) : "l"(a), "l"(b), "l"(d));
}

// ================= k-pair FMA2 GEMM kernels =================
// 64x64 tile, 4x4 outputs/thread, acc = lane-paired partial sums (even-k, odd-k).
// Per k-pair: 4 LDS.128 + 16 FMA2, no dup movs.

// ---------------- K1: QKV ----------------
// grid (8, 64, 3), block (16,16)
__global__ void k_qkv(const float* __restrict__ A,
                      const float* __restrict__ Wq, const float* __restrict__ bq,
                      const float* __restrict__ Wk, const float* __restrict__ bk,
                      const float* __restrict__ Wv, const float* __restrict__ bv)
{
    __shared__ __align__(16) ull As2[8][66];
    __shared__ __align__(16) ull Bs2[8][66];
    int which = blockIdx.z;
    const float* W    = (which==0)?Wq:((which==1)?Wk:Wv);
    const float* bias = (which==0)?bq:((which==1)?bk:bv);
    float* C          = (which==0)?g_q:((which==1)?g_k:g_v);
    int m0 = blockIdx.y*64, n0 = blockIdx.x*64;
    int tx = threadIdx.x, ty = threadIdx.y;
    int tid = ty*16 + tx;
    int kpA = tid & 7, ma = tid >> 3;          // A fill: 2 m's (ma, ma+32)
    int nn = tid & 63, kpB = tid >> 6;         // B fill: kp's (kpB, kpB+4)
    ull acc[4][4];
    #pragma unroll
    for (int i=0;i<4;i++)
        #pragma unroll
        for (int j=0;j<4;j++) acc[i][j]=0ull;
    float2 pa0, pa1; float pb0a, pb0b, pb1a, pb1b;
    pa0 = *(const float2*)&A[(size_t)(m0 + ma     )*DMODEL + 2*kpA];
    pa1 = *(const float2*)&A[(size_t)(m0 + ma + 32)*DMODEL + 2*kpA];
    pb0a = W[(size_t)(2*kpB    )*DMODEL + n0 + nn];
    pb0b = W[(size_t)(2*kpB + 1)*DMODEL + n0 + nn];
    pb1a = W[(size_t)(2*kpB + 8)*DMODEL + n0 + nn];
    pb1b = W[(size_t)(2*kpB + 9)*DMODEL + n0 + nn];
    for (int k0 = 0; k0 < DMODEL; k0 += 16) {
        As2[kpA][ma]      = pk2(pa0.x, pa0.y);
        As2[kpA][ma + 32] = pk2(pa1.x, pa1.y);
        Bs2[kpB    ][nn]  = pk2(pb0a, pb0b);
        Bs2[kpB + 4][nn]  = pk2(pb1a, pb1b);
        __syncthreads();
        if (k0 + 16 < DMODEL){
            int kn = k0 + 16;
            pa0 = *(const float2*)&A[(size_t)(m0 + ma     )*DMODEL + kn + 2*kpA];
            pa1 = *(const float2*)&A[(size_t)(m0 + ma + 32)*DMODEL + kn + 2*kpA];
            pb0a = W[(size_t)(kn + 2*kpB    )*DMODEL + n0 + nn];
            pb0b = W[(size_t)(kn + 2*kpB + 1)*DMODEL + n0 + nn];
            pb1a = W[(size_t)(kn + 2*kpB + 8)*DMODEL + n0 + nn];
            pb1b = W[(size_t)(kn + 2*kpB + 9)*DMODEL + n0 + nn];
        }
        #pragma unroll
        for (int kp=0; kp<8; kp++) {
            ulonglong2 a01 = *(const ulonglong2*)&As2[kp][ty*4];
            ulonglong2 a23 = *(const ulonglong2*)&As2[kp][ty*4+2];
            ulonglong2 b01 = *(const ulonglong2*)&Bs2[kp][tx*4];
            ulonglong2 b23 = *(const ulonglong2*)&Bs2[kp][tx*4+2];
            ull aa[4] = {a01.x, a01.y, a23.x, a23.y};
            ull bb[4] = {b01.x, b01.y, b23.x, b23.y};
            #pragma unroll
            for (int i=0;i<4;i++)
                #pragma unroll
                for (int j=0;j<4;j++) fma2(acc[i][j], aa[i], bb[j]);
        }
        __syncthreads();
    }
    #pragma unroll
    for (int i=0;i<4;i++){
        int row = m0 + ty*4 + i;
        int bidx = row >> 9, nidx = row & 511;
        #pragma unroll
        for (int j=0;j<4;j++){
            float lo, hi; upk2(acc[i][j], lo, hi);
            int c = n0 + tx*4 + j;
            int h = c >> 6, dh = c & 63;
            C[(((size_t)(bidx*HH + h))*NSEQ + nidx)*DHD + dh] = lo + hi + bias[c];
        }
    }
}

// ---------------- K2: qp (unchanged) ----------------
__global__ void k_qp(const float* __restrict__ posk)
{
    __shared__ __align__(16) float As[16][68];
    __shared__ __align__(16) float Bs[16][132];
    int m0 = blockIdx.x * 64;
    int tx = threadIdx.x, ty = threadIdx.y;
    int tid = ty*16 + tx;
    int kk = tid & 15, mrow = tid >> 4;
    int r = tid & 127, kh = tid >> 7;
    ull acc[4][4];
    #pragma unroll
    for (int i=0;i<4;i++){ acc[i][0]=0ull; acc[i][1]=0ull; acc[i][2]=0ull; acc[i][3]=0ull; }
    float pa[4], pb[8];
    #pragma unroll
    for (int i=0;i<4;i++) pa[i] = g_q[(size_t)(m0 + mrow + 16*i)*64 + kk];
    #pragma unroll
    for (int j=0;j<8;j++) pb[j] = (r < NPOS) ? posk[r*64 + kh*8 + j] : 0.f;
    for (int k0 = 0; k0 < 64; k0 += 16) {
        #pragma unroll
        for (int i=0;i<4;i++) As[kk][mrow + 16*i] = pa[i];
        #pragma unroll
        for (int j=0;j<8;j++) Bs[kh*8+j][r] = pb[j];
        __syncthreads();
        if (k0 + 16 < 64){
            #pragma unroll
            for (int i=0;i<4;i++) pa[i] = g_q[(size_t)(m0 + mrow + 16*i)*64 + k0 + 16 + kk];
            #pragma unroll
            for (int j=0;j<8;j++) pb[j] = (r < NPOS) ? posk[r*64 + k0 + 16 + kh*8 + j] : 0.f;
        }
        #pragma unroll
        for (int k2=0; k2<16; k2++){
            float4 a  = *(const float4*)&As[k2][ty*4];
            ulonglong2 b0 = *(const ulonglong2*)&Bs[k2][tx*8];
            ulonglong2 b1 = *(const ulonglong2*)&Bs[k2][tx*8+4];
            ull aa[4] = {pk2(a.x,a.x), pk2(a.y,a.y), pk2(a.z,a.z), pk2(a.w,a.w)};
            #pragma unroll
            for (int i=0;i<4;i++){
                fma2(acc[i][0], aa[i], b0.x); fma2(acc[i][1], aa[i], b0.y);
                fma2(acc[i][2], aa[i], b1.x); fma2(acc[i][3], aa[i], b1.y);
            }
        }
        __syncthreads();
    }
    #pragma unroll
    for (int i=0;i<4;i++){
        int row = m0 + ty*4 + i;
        float v[8];
        #pragma unroll
        for (int j=0;j<4;j++) upk2(acc[i][j], v[2*j], v[2*j+1]);
        #pragma unroll
        for (int j=0;j<8;j++){
            int c = tx*8 + j;
            if (c < NPOS) g_qp[(size_t)row*128 + c] = v[j];
        }
    }
}

// ---------------- K3: scores, k-pair GEMM, K=64 ----------------
// grid (8, 8, 64), block (16,16)
__global__ void k_scores()
{
    __shared__ __align__(16) ull As2[8][66];
    __shared__ __align__(16) ull Bs2[8][66];
    int bh = blockIdx.z;
    const float* qb  = g_q  + (size_t)bh*NSEQ*DHD;
    const float* kb_ = g_k  + (size_t)bh*NSEQ*DHD;
    const float* qpb = g_qp + (size_t)bh*NSEQ*128;
    float* outb = g_maps + (size_t)bh*NSEQ*NSEQ;
    int n0 = blockIdx.y*64, m0 = blockIdx.x*64;
    int tx = threadIdx.x, ty = threadIdx.y;
    int tid = ty*16 + tx;
    int kpA = tid & 7, ma = tid >> 3;
    ull acc[4][4];
    #pragma unroll
    for (int i=0;i<4;i++)
        #pragma unroll
        for (int j=0;j<4;j++) acc[i][j]=0ull;
    float2 pa0, pa1, pb0, pb1;
    pa0 = *(const float2*)&qb [(size_t)(n0 + ma     )*DHD + 2*kpA];
    pa1 = *(const float2*)&qb [(size_t)(n0 + ma + 32)*DHD + 2*kpA];
    pb0 = *(const float2*)&kb_[(size_t)(m0 + ma     )*DHD + 2*kpA];
    pb1 = *(const float2*)&kb_[(size_t)(m0 + ma + 32)*DHD + 2*kpA];
    for (int k0 = 0; k0 < DHD; k0 += 16) {
        As2[kpA][ma]      = pk2(pa0.x, pa0.y);
        As2[kpA][ma + 32] = pk2(pa1.x, pa1.y);
        Bs2[kpA][ma]      = pk2(pb0.x, pb0.y);
        Bs2[kpA][ma + 32] = pk2(pb1.x, pb1.y);
        __syncthreads();
        if (k0 + 16 < DHD){
            int kn = k0 + 16;
            pa0 = *(const float2*)&qb [(size_t)(n0 + ma     )*DHD + kn + 2*kpA];
            pa1 = *(const float2*)&qb [(size_t)(n0 + ma + 32)*DHD + kn + 2*kpA];
            pb0 = *(const float2*)&kb_[(size_t)(m0 + ma     )*DHD + kn + 2*kpA];
            pb1 = *(const float2*)&kb_[(size_t)(m0 + ma + 32)*DHD + kn + 2*kpA];
        }
        #pragma unroll
        for (int kp=0; kp<8; kp++){
            ulonglong2 a01 = *(const ulonglong2*)&As2[kp][ty*4];
            ulonglong2 a23 = *(const ulonglong2*)&As2[kp][ty*4+2];
            ulonglong2 b01 = *(const ulonglong2*)&Bs2[kp][tx*4];
            ulonglong2 b23 = *(const ulonglong2*)&Bs2[kp][tx*4+2];
            ull aa[4] = {a01.x, a01.y, a23.x, a23.y};
            ull bb[4] = {b01.x, b01.y, b23.x, b23.y};
            #pragma unroll
            for (int i=0;i<4;i++)
                #pragma unroll
                for (int j=0;j<4;j++) fma2(acc[i][j], aa[i], bb[j]);
        }
        __syncthreads();
    }
    #pragma unroll
    for (int i=0;i<4;i++){
        int n = n0 + ty*4 + i;
        #pragma unroll
        for (int j=0;j<4;j++){
            float lo, hi; upk2(acc[i][j], lo, hi);
            int m = m0 + tx*4 + j;
            int rel = m - n;
            rel = min(60, max(-60, rel)) + 60;
            outb[(size_t)n*NSEQ + m] = (lo + hi + qpb[(size_t)n*128 + rel]) * 0.125f;
        }
    }
}

// ---------------- conv 5x5 (R11/R14 exact) ----------------
template<int IC, int OCBLKS, int OCTOT, bool ACT, bool STATS>
__global__ void __launch_bounds__(256,4) k_conv(const float* __restrict__ w, const float* __restrict__ bias,
                                                const int* __restrict__ valid_len)
{
    __shared__ __align__(16) float patch[36*40];
    __shared__ ull ws[25*IC*4];
    __shared__ float sc[IC], sh[IC];
    const float* in = ACT ? g_y1 : g_maps;
    float* out      = ACT ? g_maps : g_y1;
    int z   = blockIdx.z;
    int bb  = z / OCBLKS;
    int oc0 = (z % OCBLKS) * 8;
    int x0 = blockIdx.x*32, y0 = blockIdx.y*32;
    int tid = threadIdx.x;
    int tx = tid & 7, ty = tid >> 3;
    for (int idx = tid; idx < 25*IC*4; idx += 256){
        int jp = idx & 3; int rest = idx >> 2;
        int ic = rest % IC; int t = rest / IC;
        const float* wp = w + ((size_t)(t*IC + ic))*OCTOT + oc0 + 2*jp;
        ws[idx] = pk2(wp[0], wp[1]);
    }
    if (ACT && tid < IC){
        sc[tid] = g_nrm[(bb*IC + tid)*2];
        sh[tid] = g_nrm[(bb*IC + tid)*2 + 1];
    }
    ull acc[4][4];
    #pragma unroll
    for (int i=0;i<4;i++)
        #pragma unroll
        for (int jp=0;jp<4;jp++) acc[i][jp] = pk2(bias[oc0+2*jp], bias[oc0+2*jp+1]);

    float pre[6];
    {
        const float* ip = in + ((size_t)(bb*IC))*NSEQ*NSEQ;
        #pragma unroll
        for (int it=0; it<6; it++){
            int idx = tid + 256*it;
            float v = 0.f;
            if (idx < 1296){
                int rrw = idx / 36, cc = idx - rrw*36;
                int gy = y0 - 2 + rrw, gx = x0 - 2 + cc;
                if ((unsigned)gy < NSEQ && (unsigned)gx < NSEQ) v = ip[(size_t)gy*NSEQ + gx];
            }
            pre[it] = v;
        }
    }
    for (int ic = 0; ic < IC; ic++){
        __syncthreads();
        {
            float scv = ACT ? sc[ic] : 0.f;
            float shv = ACT ? sh[ic] : 0.f;
            #pragma unroll
            for (int it=0; it<6; it++){
                int idx = tid + 256*it;
                if (idx < 1296){
                    int rrw = idx / 36, cc = idx - rrw*36;
                    float v = pre[it];
                    if (ACT){
                        int gy = y0 - 2 + rrw, gx = x0 - 2 + cc;
                        v = ((unsigned)gy < NSEQ && (unsigned)gx < NSEQ)
                            ? fmaxf(fmaf(v, scv, shv), 0.f) : 0.f;
                    }
                    patch[rrw*40 + cc] = v;
                }
            }
        }
        __syncthreads();
        if (ic + 1 < IC){
            const float* ip = in + ((size_t)(bb*IC + ic + 1))*NSEQ*NSEQ;
            #pragma unroll
            for (int it=0; it<6; it++){
                int idx = tid + 256*it;
                float v = 0.f;
                if (idx < 1296){
                    int rrw = idx / 36, cc = idx - rrw*36;
                    int gy = y0 - 2 + rrw, gx = x0 - 2 + cc;
                    if ((unsigned)gy < NSEQ && (unsigned)gx < NSEQ) v = ip[(size_t)gy*NSEQ + gx];
                }
                pre[it] = v;
            }
        }
        #pragma unroll
        for (int ky=0; ky<5; ky++){
            const float4* pr = (const float4*)&patch[(ty+ky)*40 + tx*4];
            float pf[8];
            *(float4*)&pf[0] = pr[0];
            *(float4*)&pf[4] = pr[1];
            #pragma unroll
            for (int kx=0; kx<5; kx++){
                const ull* wp = &ws[((ky*5+kx)*IC + ic)*4];
                ull w0 = wp[0], w1 = wp[1], w2 = wp[2], w3 = wp[3];
                #pragma unroll
                for (int i=0;i<4;i++){
                    ull pv = pk2(pf[i+kx], pf[i+kx]);
                    fma2(acc[i][0], pv, w0);
                    fma2(acc[i][1], pv, w1);
                    fma2(acc[i][2], pv, w2);
                    fma2(acc[i][3], pv, w3);
                }
            }
        }
    }
    int y = y0 + ty;
    float st[16];
    bool vrow = STATS ? (y < valid_len[bb]) : false;
    #pragma unroll
    for (int jp=0;jp<4;jp++){
        float lo[4], hi[4];
        #pragma unroll
        for (int i=0;i<4;i++) upk2(acc[i][jp], lo[i], hi[i]);
        float4 vlo = {lo[0],lo[1],lo[2],lo[3]};
        float4 vhi = {hi[0],hi[1],hi[2],hi[3]};
        *(float4*)&out[(((size_t)(bb*OCTOT + oc0 + 2*jp    ))*NSEQ + y)*NSEQ + x0 + tx*4] = vlo;
        *(float4*)&out[(((size_t)(bb*OCTOT + oc0 + 2*jp + 1))*NSEQ + y)*NSEQ + x0 + tx*4] = vhi;
        if (STATS){
            float s0=0.f,q0=0.f,s1=0.f,q1=0.f;
            #pragma unroll
            for (int i=0;i<4;i++){
                s0 += lo[i]; q0 += lo[i]*lo[i];
                s1 += hi[i]; q1 += hi[i]*hi[i];
            }
            if (!vrow){ s0=q0=s1=q1=0.f; }
            st[jp*4+0]=s0; st[jp*4+1]=q0; st[jp*4+2]=s1; st[jp*4+3]=q1;
        }
    }
    if (STATS){
        __syncthreads();
        float* red = patch;
        #pragma unroll
        for (int t=0;t<16;t++){
            float v = st[t];
            #pragma unroll
            for (int o=16;o;o>>=1) v += __shfl_xor_sync(0xffffffffu, v, o);
            st[t] = v;
        }
        int wid = tid >> 5, lane = tid & 31;
        if (lane == 0){
            #pragma unroll
            for (int t=0;t<16;t++) red[wid*16 + t] = st[t];
        }
        __syncthreads();
        if (tid < 16){
            float rs = 0.f;
            #pragma unroll
            for (int wdx=0; wdx<8; wdx++) rs += red[wdx*16 + tid];
            int jp = tid >> 2;
            int sub = tid & 3;
            int ch = oc0 + 2*jp + (sub>>1);
            int tile = blockIdx.y*16 + blockIdx.x;
            g_part[((size_t)(bb*16 + ch)*256 + tile)*2 + (sub&1)] = rs;
        }
    }
}

// ---------------- norm finalize ----------------
__global__ void k_nrm(const int* __restrict__ valid_len,
                      const float* __restrict__ gamma, const float* __restrict__ beta)
{
    __shared__ float ss[256], qq[256];
    int bc = blockIdx.x;
    int i = threadIdx.x;
    ss[i] = g_part[((size_t)bc*256 + i)*2];
    qq[i] = g_part[((size_t)bc*256 + i)*2 + 1];
    __syncthreads();
    for (int o = 128; o; o >>= 1){
        if (i < o){ ss[i] += ss[i+o]; qq[i] += qq[i+o]; }
        __syncthreads();
    }
    if (i == 0){
        int b = bc >> 4, c = bc & 15;
        float cnt = (float)valid_len[b] * (float)NSEQ;
        float mean = ss[0] / cnt;
        float var = fmaxf(qq[0] / cnt - mean*mean, 0.f);
        float scale = gamma[c] * rsqrtf(var + EPSF);
        g_nrm[bc*2]     = scale;
        g_nrm[bc*2 + 1] = beta[c] - mean*scale;
    }
}

// ---------------- masked softmax ----------------
__global__ void k_softmax(const int* __restrict__ valid_len)
{
    int warp = threadIdx.x >> 5, lane = threadIdx.x & 31;
    int row = blockIdx.x*8 + warp;
    int b = row >> 12;
    int valid = valid_len[b];
    float* p = g_maps + (size_t)row*NSEQ;
    float v[16]; float mx = -1e30f;
    #pragma unroll
    for (int j=0;j<16;j++){
        int m = lane + 32*j;
        float x = (m < valid) ? p[m] : -1e30f;
        v[j] = x; mx = fmaxf(mx, x);
    }
    #pragma unroll
    for (int o=16;o;o>>=1) mx = fmaxf(mx, __shfl_xor_sync(0xffffffffu, mx, o));
    float s = 0.f;
    #pragma unroll
    for (int j=0;j<16;j++){
        int m = lane + 32*j;
        float e = (m < valid) ? __expf(v[j]-mx) : 0.f;
        v[j] = e; s += e;
    }
    #pragma unroll
    for (int o=16;o;o>>=1) s += __shfl_xor_sync(0xffffffffu, s, o);
    float inv = 1.f / s;
    #pragma unroll
    for (int j=0;j<16;j++) p[lane + 32*j] = v[j]*inv;
}

// ---------------- attn @ V -> ctx, k-pair GEMM, K=512, N=64 ----------------
// grid (1, 8, 64), block (16,16)
__global__ void k_av()
{
    __shared__ __align__(16) ull As2[8][66];
    __shared__ __align__(16) ull Bs2[8][66];
    int bh = blockIdx.z;
    const float* ab = g_maps + (size_t)bh*NSEQ*NSEQ;
    const float* vb = g_v    + (size_t)bh*NSEQ*DHD;
    int n0 = blockIdx.y*64;
    int tx = threadIdx.x, ty = threadIdx.y;
    int tid = ty*16 + tx;
    int kpA = tid & 7, ma = tid >> 3;
    int dd = tid & 63, kpB = tid >> 6;
    ull acc[4][4];
    #pragma unroll
    for (int i=0;i<4;i++)
        #pragma unroll
        for (int j=0;j<4;j++) acc[i][j]=0ull;
    float2 pa0, pa1; float pb0a, pb0b, pb1a, pb1b;
    pa0 = *(const float2*)&ab[(size_t)(n0 + ma     )*NSEQ + 2*kpA];
    pa1 = *(const float2*)&ab[(size_t)(n0 + ma + 32)*NSEQ + 2*kpA];
    pb0a = vb[(size_t)(2*kpB    )*DHD + dd];
    pb0b = vb[(size_t)(2*kpB + 1)*DHD + dd];
    pb1a = vb[(size_t)(2*kpB + 8)*DHD + dd];
    pb1b = vb[(size_t)(2*kpB + 9)*DHD + dd];
    for (int k0 = 0; k0 < NSEQ; k0 += 16){
        As2[kpA][ma]      = pk2(pa0.x, pa0.y);
        As2[kpA][ma + 32] = pk2(pa1.x, pa1.y);
        Bs2[kpB    ][dd]  = pk2(pb0a, pb0b);
        Bs2[kpB + 4][dd]  = pk2(pb1a, pb1b);
        __syncthreads();
        if (k0 + 16 < NSEQ){
            int kn = k0 + 16;
            pa0 = *(const float2*)&ab[(size_t)(n0 + ma     )*NSEQ + kn + 2*kpA];
            pa1 = *(const float2*)&ab[(size_t)(n0 + ma + 32)*NSEQ + kn + 2*kpA];
            pb0a = vb[(size_t)(kn + 2*kpB    )*DHD + dd];
            pb0b = vb[(size_t)(kn + 2*kpB + 1)*DHD + dd];
            pb1a = vb[(size_t)(kn + 2*kpB + 8)*DHD + dd];
            pb1b = vb[(size_t)(kn + 2*kpB + 9)*DHD + dd];
        }
        #pragma unroll
        for (int kp=0; kp<8; kp++){
            ulonglong2 a01 = *(const ulonglong2*)&As2[kp][ty*4];
            ulonglong2 a23 = *(const ulonglong2*)&As2[kp][ty*4+2];
            ulonglong2 b01 = *(const ulonglong2*)&Bs2[kp][tx*4];
            ulonglong2 b23 = *(const ulonglong2*)&Bs2[kp][tx*4+2];
            ull aa[4] = {a01.x, a01.y, a23.x, a23.y};
            ull bb[4] = {b01.x, b01.y, b23.x, b23.y};
            #pragma unroll
            for (int i=0;i<4;i++)
                #pragma unroll
                for (int j=0;j<4;j++) fma2(acc[i][j], aa[i], bb[j]);
        }
        __syncthreads();
    }
    int b = bh >> 3, h = bh & 7;
    #pragma unroll
    for (int i=0;i<4;i++){
        int n = n0 + ty*4 + i;
        #pragma unroll
        for (int j=0;j<4;j++){
            float lo, hi; upk2(acc[i][j], lo, hi);
            int d = h*64 + tx*4 + j;
            g_ctx[((size_t)(b*NSEQ + n))*DMODEL + d] = lo + hi;
        }
    }
}

// ---------------- out = ctx @ Wh + bh + query, k-pair GEMM ----------------
// grid (8, 64), block (16,16)
__global__ void k_out(const float* __restrict__ Wh, const float* __restrict__ bhv,
                      const float* __restrict__ query)
{
    __shared__ __align__(16) ull As2[8][66];
    __shared__ __align__(16) ull Bs2[8][66];
    int m0 = blockIdx.y*64, n0 = blockIdx.x*64;
    int tx = threadIdx.x, ty = threadIdx.y;
    int tid = ty*16 + tx;
    int kpA = tid & 7, ma = tid >> 3;
    int nn = tid & 63, kpB = tid >> 6;
    ull acc[4][4];
    #pragma unroll
    for (int i=0;i<4;i++)
        #pragma unroll
        for (int j=0;j<4;j++) acc[i][j]=0ull;
    float2 pa0, pa1; float pb0a, pb0b, pb1a, pb1b;
    pa0 = *(const float2*)&g_ctx[(size_t)(m0 + ma     )*DMODEL + 2*kpA];
    pa1 = *(const float2*)&g_ctx[(size_t)(m0 + ma + 32)*DMODEL + 2*kpA];
    pb0a = Wh[(size_t)(2*kpB    )*DMODEL + n0 + nn];
    pb0b = Wh[(size_t)(2*kpB + 1)*DMODEL + n0 + nn];
    pb1a = Wh[(size_t)(2*kpB + 8)*DMODEL + n0 + nn];
    pb1b = Wh[(size_t)(2*kpB + 9)*DMODEL + n0 + nn];
    for (int k0 = 0; k0 < DMODEL; k0 += 16){
        As2[kpA][ma]      = pk2(pa0.x, pa0.y);
        As2[kpA][ma + 32] = pk2(pa1.x, pa1.y);
        Bs2[kpB    ][nn]  = pk2(pb0a, pb0b);
        Bs2[kpB + 4][nn]  = pk2(pb1a, pb1b);
        __syncthreads();
        if (k0 + 16 < DMODEL){
            int kn = k0 + 16;
            pa0 = *(const float2*)&g_ctx[(size_t)(m0 + ma     )*DMODEL + kn + 2*kpA];
            pa1 = *(const float2*)&g_ctx[(size_t)(m0 + ma + 32)*DMODEL + kn + 2*kpA];
            pb0a = Wh[(size_t)(kn + 2*kpB    )*DMODEL + n0 + nn];
            pb0b = Wh[(size_t)(kn + 2*kpB + 1)*DMODEL + n0 + nn];
            pb1a = Wh[(size_t)(kn + 2*kpB + 8)*DMODEL + n0 + nn];
            pb1b = Wh[(size_t)(kn + 2*kpB + 9)*DMODEL + n0 + nn];
        }
        #pragma unroll
        for (int kp=0; kp<8; kp++){
            ulonglong2 a01 = *(const ulonglong2*)&As2[kp][ty*4];
            ulonglong2 a23 = *(const ulonglong2*)&As2[kp][ty*4+2];
            ulonglong2 b01 = *(const ulonglong2*)&Bs2[kp][tx*4];
            ulonglong2 b23 = *(const ulonglong2*)&Bs2[kp][tx*4+2];
            ull aa[4] = {a01.x, a01.y, a23.x, a23.y};
            ull bb[4] = {b01.x, b01.y, b23.x, b23.y};
            #pragma unroll
            for (int i=0;i<4;i++)
                #pragma unroll
                for (int j=0;j<4;j++) fma2(acc[i][j], aa[i], bb[j]);
        }
        __syncthreads();
    }
    #pragma unroll
    for (int i=0;i<4;i++){
        int row = m0 + ty*4 + i;
        #pragma unroll
        for (int j=0;j<4;j++){
            float lo, hi; upk2(acc[i][j], lo, hi);
            int c = n0 + tx*4 + j;
            g_tmp[(size_t)row*DMODEL + c] = lo + hi + bhv[c] + query[(size_t)row*DMODEL + c];
        }
    }
}

// ---------------- final layernorm ----------------
__global__ void k_ln(const float* __restrict__ gamma, const float* __restrict__ beta,
                     float* __restrict__ out)
{
    int warp = threadIdx.x >> 5, lane = threadIdx.x & 31;
    int row = blockIdx.x*8 + warp;
    const float* p = g_tmp + (size_t)row*DMODEL;
    float v[16]; float s = 0.f;
    #pragma unroll
    for (int j=0;j<16;j++){ v[j] = p[lane + 32*j]; s += v[j]; }
    #pragma unroll
    for (int o=16;o;o>>=1) s += __shfl_xor_sync(0xffffffffu, s, o);
    float mean = s * (1.f/512.f);
    float q = 0.f;
    #pragma unroll
    for (int j=0;j<16;j++){ float d = v[j]-mean; q += d*d; }
    #pragma unroll
    for (int o=16;o;o>>=1) q += __shfl_xor_sync(0xffffffffu, q, o);
    float rstd = rsqrtf(q * (1.f/512.f) + EPSF);
    #pragma unroll
    for (int j=0;j<16;j++){
        int c = lane + 32*j;
        out[(size_t)row*DMODEL + c] = gamma[c]*(v[j]-mean)*rstd + beta[c];
    }
}

// ---------------- launch ----------------
extern "C" void kernel_launch(void* const* d_in, const int* in_sizes, int n_in,
                              void* d_out, int out_size)
{
    const float* query   = (const float*)d_in[0];
    const int*   valid   = (const int*)  d_in[1];
    const float* Wq      = (const float*)d_in[2];
    const float* bq      = (const float*)d_in[3];
    const float* Wk      = (const float*)d_in[4];
    const float* bk      = (const float*)d_in[5];
    const float* Wv      = (const float*)d_in[6];
    const float* bv      = (const float*)d_in[7];
    const float* Wh      = (const float*)d_in[8];
    const float* bhv     = (const float*)d_in[9];
    const float* pos_k   = (const float*)d_in[10];
    const float* conv1_w = (const float*)d_in[11];
    const float* conv1_b = (const float*)d_in[12];
    const float* n1g     = (const float*)d_in[13];
    const float* n1b     = (const float*)d_in[14];
    const float* conv2_w = (const float*)d_in[15];
    const float* conv2_b = (const float*)d_in[16];
    const float* lng     = (const float*)d_in[17];
    const float* lnb     = (const float*)d_in[18];
    float* outp = (float*)d_out;

    dim3 t16(16,16);
    k_qkv   <<<dim3(8,64,3),  t16>>>(query, Wq,bq, Wk,bk, Wv,bv);
    k_qp    <<<dim3(512,1,1), t16>>>(pos_k);
    k_scores<<<dim3(8,8,64),  t16>>>();
    k_conv<8,2,16,false,true><<<dim3(16,16,16), 256>>>(conv1_w, conv1_b, valid);
    k_nrm   <<<128, 256>>>(valid, n1g, n1b);
    k_conv<16,1,8,true,false><<<dim3(16,16,8), 256>>>(conv2_w, conv2_b, valid);
    k_softmax<<<4096, 256>>>(valid);
    k_av    <<<dim3(1,8,64),  t16>>>();
    k_out   <<<dim3(8,64),    t16>>>(Wh, bhv, query);
    k_ln    <<<512, 256>>>(lng, lnb, outp);
}

// round 16
// speedup vs baseline: 1.2904x; 1.2904x over previous
#include <cuda_runtime.h>
#include <math.h>

#define BB   8
#define NSEQ 512
#define DMODEL 512
#define HH   8
#define DHD  64
#define NPOS 121
#define EPSF 1e-7f

typedef unsigned long long ull;

// ---------------- scratch ----------------
__device__ float g_q [BB*HH*NSEQ*DHD];
__device__ float g_k [BB*HH*NSEQ*DHD];
__device__ float g_v [BB*HH*NSEQ*DHD];
__device__ float g_qp[BB*HH*NSEQ*128];
__device__ float g_maps[(size_t)BB*HH*NSEQ*NSEQ];
__device__ float g_y1  [(size_t)BB*16*NSEQ*NSEQ];
__device__ float g_part[128*256*2];
__device__ float g_nrm [128*2];
__device__ float2 g_sstat[BB*HH*NSEQ];            // per-row (max, 1/sum)
__device__ float g_ctx [BB*NSEQ*DMODEL];
__device__ float g_tmp [BB*NSEQ*DMODEL];

// ---------------- f32x2 helpers ----------------
__device__ __forceinline__ ull pk2(float a, float b){
    ull r; asm("mov.b64 %0, {%1,%2};" : "=l"(r) : "f"(a), "f"(b)); return r;
}
__device__ __forceinline__ void upk2(ull v, float& a, float& b){
    asm("mov.b64 {%0,%1}, %2;" : "=f"(a), "=f"(b) : "l"(v));
}
__device__ __forceinline__ void fma2(ull& d, ull a, ull b){
    asm("fma.rn.f32x2 %0, %1, %2, %3;" : "=l"(d) : "l"(a), "l"(b), "l"(d));
}

// ---------------- K1: QKV, 64x64 tile, K-slab 32, reg double-buffered ----------------
// grid (8, 64, 3), block (16,16)
__global__ void k_qkv(const float* __restrict__ A,
                      const float* __restrict__ Wq, const float* __restrict__ bq,
                      const float* __restrict__ Wk, const float* __restrict__ bk,
                      const float* __restrict__ Wv, const float* __restrict__ bv)
{
    __shared__ __align__(16) float As[32][68];
    __shared__ __align__(16) float Bs[32][68];
    int which = blockIdx.z;
    const float* W    = (which==0)?Wq:((which==1)?Wk:Wv);
    const float* bias = (which==0)?bq:((which==1)?bk:bv);
    float* C          = (which==0)?g_q:((which==1)?g_k:g_v);
    int m0 = blockIdx.y*64, n0 = blockIdx.x*64;
    int tx = threadIdx.x, ty = threadIdx.y;
    int tid = ty*16 + tx;
    int kk = tid & 31, mseg = tid >> 5;
    int nn = tid & 63, kb = tid >> 6;
    ull acc[4][2];
    #pragma unroll
    for (int i=0;i<4;i++){ acc[i][0]=0ull; acc[i][1]=0ull; }
    float pa[8], pb[8];
    #pragma unroll
    for (int i=0;i<8;i++) pa[i] = A[(size_t)(m0 + mseg + 8*i)*DMODEL + kk];
    #pragma unroll
    for (int j=0;j<8;j++) pb[j] = W[(size_t)(kb*8 + j)*DMODEL + n0 + nn];
    for (int k0 = 0; k0 < DMODEL; k0 += 32) {
        #pragma unroll
        for (int i=0;i<8;i++) As[kk][mseg + 8*i] = pa[i];
        #pragma unroll
        for (int j=0;j<8;j++) Bs[kb*8+j][nn] = pb[j];
        __syncthreads();
        if (k0 + 32 < DMODEL){
            #pragma unroll
            for (int i=0;i<8;i++) pa[i] = A[(size_t)(m0 + mseg + 8*i)*DMODEL + k0 + 32 + kk];
            #pragma unroll
            for (int j=0;j<8;j++) pb[j] = W[(size_t)(k0 + 32 + kb*8 + j)*DMODEL + n0 + nn];
        }
        #pragma unroll
        for (int k2=0; k2<32; k2++) {
            float4 a = *(const float4*)&As[k2][ty*4];
            ulonglong2 b = *(const ulonglong2*)&Bs[k2][tx*4];
            ull aa[4] = {pk2(a.x,a.x), pk2(a.y,a.y), pk2(a.z,a.z), pk2(a.w,a.w)};
            #pragma unroll
            for (int i=0;i<4;i++){ fma2(acc[i][0], aa[i], b.x); fma2(acc[i][1], aa[i], b.y); }
        }
        __syncthreads();
    }
    #pragma unroll
    for (int i=0;i<4;i++){
        int row = m0 + ty*4 + i;
        int bidx = row >> 9, nidx = row & 511;
        float v[4]; upk2(acc[i][0], v[0], v[1]); upk2(acc[i][1], v[2], v[3]);
        #pragma unroll
        for (int j=0;j<4;j++){
            int c = n0 + tx*4 + j;
            int h = c >> 6, dh = c & 63;
            C[(((size_t)(bidx*HH + h))*NSEQ + nidx)*DHD + dh] = v[j] + bias[c];
        }
    }
}

// ---------------- K2: qp ----------------
__global__ void k_qp(const float* __restrict__ posk)
{
    __shared__ __align__(16) float As[16][68];
    __shared__ __align__(16) float Bs[16][132];
    int m0 = blockIdx.x * 64;
    int tx = threadIdx.x, ty = threadIdx.y;
    int tid = ty*16 + tx;
    int kk = tid & 15, mrow = tid >> 4;
    int r = tid & 127, kh = tid >> 7;
    ull acc[4][4];
    #pragma unroll
    for (int i=0;i<4;i++){ acc[i][0]=0ull; acc[i][1]=0ull; acc[i][2]=0ull; acc[i][3]=0ull; }
    float pa[4], pb[8];
    #pragma unroll
    for (int i=0;i<4;i++) pa[i] = g_q[(size_t)(m0 + mrow + 16*i)*64 + kk];
    #pragma unroll
    for (int j=0;j<8;j++) pb[j] = (r < NPOS) ? posk[r*64 + kh*8 + j] : 0.f;
    for (int k0 = 0; k0 < 64; k0 += 16) {
        #pragma unroll
        for (int i=0;i<4;i++) As[kk][mrow + 16*i] = pa[i];
        #pragma unroll
        for (int j=0;j<8;j++) Bs[kh*8+j][r] = pb[j];
        __syncthreads();
        if (k0 + 16 < 64){
            #pragma unroll
            for (int i=0;i<4;i++) pa[i] = g_q[(size_t)(m0 + mrow + 16*i)*64 + k0 + 16 + kk];
            #pragma unroll
            for (int j=0;j<8;j++) pb[j] = (r < NPOS) ? posk[r*64 + k0 + 16 + kh*8 + j] : 0.f;
        }
        #pragma unroll
        for (int k2=0; k2<16; k2++){
            float4 a  = *(const float4*)&As[k2][ty*4];
            ulonglong2 b0 = *(const ulonglong2*)&Bs[k2][tx*8];
            ulonglong2 b1 = *(const ulonglong2*)&Bs[k2][tx*8+4];
            ull aa[4] = {pk2(a.x,a.x), pk2(a.y,a.y), pk2(a.z,a.z), pk2(a.w,a.w)};
            #pragma unroll
            for (int i=0;i<4;i++){
                fma2(acc[i][0], aa[i], b0.x); fma2(acc[i][1], aa[i], b0.y);
                fma2(acc[i][2], aa[i], b1.x); fma2(acc[i][3], aa[i], b1.y);
            }
        }
        __syncthreads();
    }
    #pragma unroll
    for (int i=0;i<4;i++){
        int row = m0 + ty*4 + i;
        float v[8];
        #pragma unroll
        for (int j=0;j<4;j++) upk2(acc[i][j], v[2*j], v[2*j+1]);
        #pragma unroll
        for (int j=0;j<8;j++){
            int c = tx*8 + j;
            if (c < NPOS) g_qp[(size_t)row*128 + c] = v[j];
        }
    }
}

// ---------------- K3: scores, 64x64 tile, K-slab 32 ----------------
__global__ void k_scores()
{
    __shared__ __align__(16) float As[32][68];
    __shared__ __align__(16) float Bs[32][68];
    int bh = blockIdx.z;
    const float* qb  = g_q  + (size_t)bh*NSEQ*DHD;
    const float* kb_ = g_k  + (size_t)bh*NSEQ*DHD;
    const float* qpb = g_qp + (size_t)bh*NSEQ*128;
    float* outb = g_maps + (size_t)bh*NSEQ*NSEQ;
    int n0 = blockIdx.y*64, m0 = blockIdx.x*64;
    int tx = threadIdx.x, ty = threadIdx.y;
    int tid = ty*16 + tx;
    int kk = tid & 31, mseg = tid >> 5;
    ull acc[4][2];
    #pragma unroll
    for (int i=0;i<4;i++){ acc[i][0]=0ull; acc[i][1]=0ull; }
    float pa[8], pb[8];
    #pragma unroll
    for (int i=0;i<8;i++) pa[i] = qb [(size_t)(n0 + mseg + 8*i)*DHD + kk];
    #pragma unroll
    for (int i=0;i<8;i++) pb[i] = kb_[(size_t)(m0 + mseg + 8*i)*DHD + kk];
    for (int k0 = 0; k0 < DHD; k0 += 32) {
        #pragma unroll
        for (int i=0;i<8;i++) As[kk][mseg + 8*i] = pa[i];
        #pragma unroll
        for (int i=0;i<8;i++) Bs[kk][mseg + 8*i] = pb[i];
        __syncthreads();
        if (k0 + 32 < DHD){
            #pragma unroll
            for (int i=0;i<8;i++) pa[i] = qb [(size_t)(n0 + mseg + 8*i)*DHD + k0 + 32 + kk];
            #pragma unroll
            for (int i=0;i<8;i++) pb[i] = kb_[(size_t)(m0 + mseg + 8*i)*DHD + k0 + 32 + kk];
        }
        #pragma unroll
        for (int k2=0; k2<32; k2++){
            float4 a = *(const float4*)&As[k2][ty*4];
            ulonglong2 b = *(const ulonglong2*)&Bs[k2][tx*4];
            ull aa[4] = {pk2(a.x,a.x), pk2(a.y,a.y), pk2(a.z,a.z), pk2(a.w,a.w)};
            #pragma unroll
            for (int i=0;i<4;i++){ fma2(acc[i][0], aa[i], b.x); fma2(acc[i][1], aa[i], b.y); }
        }
        __syncthreads();
    }
    #pragma unroll
    for (int i=0;i<4;i++){
        int n = n0 + ty*4 + i;
        float v[4]; upk2(acc[i][0], v[0], v[1]); upk2(acc[i][1], v[2], v[3]);
        #pragma unroll
        for (int j=0;j<4;j++){
            int m = m0 + tx*4 + j;
            int rel = m - n;
            rel = min(60, max(-60, rel)) + 60;
            outb[(size_t)n*NSEQ + m] = (v[j] + qpb[(size_t)n*128 + rel]) * 0.125f;
        }
    }
}

// ---------------- conv 5x5 (R11/R14 exact) ----------------
template<int IC, int OCBLKS, int OCTOT, bool ACT, bool STATS>
__global__ void __launch_bounds__(256,4) k_conv(const float* __restrict__ w, const float* __restrict__ bias,
                                                const int* __restrict__ valid_len)
{
    __shared__ __align__(16) float patch[36*40];
    __shared__ ull ws[25*IC*4];
    __shared__ float sc[IC], sh[IC];
    const float* in = ACT ? g_y1 : g_maps;
    float* out      = ACT ? g_maps : g_y1;
    int z   = blockIdx.z;
    int bb  = z / OCBLKS;
    int oc0 = (z % OCBLKS) * 8;
    int x0 = blockIdx.x*32, y0 = blockIdx.y*32;
    int tid = threadIdx.x;
    int tx = tid & 7, ty = tid >> 3;
    for (int idx = tid; idx < 25*IC*4; idx += 256){
        int jp = idx & 3; int rest = idx >> 2;
        int ic = rest % IC; int t = rest / IC;
        const float* wp = w + ((size_t)(t*IC + ic))*OCTOT + oc0 + 2*jp;
        ws[idx] = pk2(wp[0], wp[1]);
    }
    if (ACT && tid < IC){
        sc[tid] = g_nrm[(bb*IC + tid)*2];
        sh[tid] = g_nrm[(bb*IC + tid)*2 + 1];
    }
    ull acc[4][4];
    #pragma unroll
    for (int i=0;i<4;i++)
        #pragma unroll
        for (int jp=0;jp<4;jp++) acc[i][jp] = pk2(bias[oc0+2*jp], bias[oc0+2*jp+1]);

    float pre[6];
    {
        const float* ip = in + ((size_t)(bb*IC))*NSEQ*NSEQ;
        #pragma unroll
        for (int it=0; it<6; it++){
            int idx = tid + 256*it;
            float v = 0.f;
            if (idx < 1296){
                int rrw = idx / 36, cc = idx - rrw*36;
                int gy = y0 - 2 + rrw, gx = x0 - 2 + cc;
                if ((unsigned)gy < NSEQ && (unsigned)gx < NSEQ) v = ip[(size_t)gy*NSEQ + gx];
            }
            pre[it] = v;
        }
    }
    for (int ic = 0; ic < IC; ic++){
        __syncthreads();
        {
            float scv = ACT ? sc[ic] : 0.f;
            float shv = ACT ? sh[ic] : 0.f;
            #pragma unroll
            for (int it=0; it<6; it++){
                int idx = tid + 256*it;
                if (idx < 1296){
                    int rrw = idx / 36, cc = idx - rrw*36;
                    float v = pre[it];
                    if (ACT){
                        int gy = y0 - 2 + rrw, gx = x0 - 2 + cc;
                        v = ((unsigned)gy < NSEQ && (unsigned)gx < NSEQ)
                            ? fmaxf(fmaf(v, scv, shv), 0.f) : 0.f;
                    }
                    patch[rrw*40 + cc] = v;
                }
            }
        }
        __syncthreads();
        if (ic + 1 < IC){
            const float* ip = in + ((size_t)(bb*IC + ic + 1))*NSEQ*NSEQ;
            #pragma unroll
            for (int it=0; it<6; it++){
                int idx = tid + 256*it;
                float v = 0.f;
                if (idx < 1296){
                    int rrw = idx / 36, cc = idx - rrw*36;
                    int gy = y0 - 2 + rrw, gx = x0 - 2 + cc;
                    if ((unsigned)gy < NSEQ && (unsigned)gx < NSEQ) v = ip[(size_t)gy*NSEQ + gx];
                }
                pre[it] = v;
            }
        }
        #pragma unroll
        for (int ky=0; ky<5; ky++){
            const float4* pr = (const float4*)&patch[(ty+ky)*40 + tx*4];
            float pf[8];
            *(float4*)&pf[0] = pr[0];
            *(float4*)&pf[4] = pr[1];
            #pragma unroll
            for (int kx=0; kx<5; kx++){
                const ull* wp = &ws[((ky*5+kx)*IC + ic)*4];
                ull w0 = wp[0], w1 = wp[1], w2 = wp[2], w3 = wp[3];
                #pragma unroll
                for (int i=0;i<4;i++){
                    ull pv = pk2(pf[i+kx], pf[i+kx]);
                    fma2(acc[i][0], pv, w0);
                    fma2(acc[i][1], pv, w1);
                    fma2(acc[i][2], pv, w2);
                    fma2(acc[i][3], pv, w3);
                }
            }
        }
    }
    int y = y0 + ty;
    float st[16];
    bool vrow = STATS ? (y < valid_len[bb]) : false;
    #pragma unroll
    for (int jp=0;jp<4;jp++){
        float lo[4], hi[4];
        #pragma unroll
        for (int i=0;i<4;i++) upk2(acc[i][jp], lo[i], hi[i]);
        float4 vlo = {lo[0],lo[1],lo[2],lo[3]};
        float4 vhi = {hi[0],hi[1],hi[2],hi[3]};
        *(float4*)&out[(((size_t)(bb*OCTOT + oc0 + 2*jp    ))*NSEQ + y)*NSEQ + x0 + tx*4] = vlo;
        *(float4*)&out[(((size_t)(bb*OCTOT + oc0 + 2*jp + 1))*NSEQ + y)*NSEQ + x0 + tx*4] = vhi;
        if (STATS){
            float s0=0.f,q0=0.f,s1=0.f,q1=0.f;
            #pragma unroll
            for (int i=0;i<4;i++){
                s0 += lo[i]; q0 += lo[i]*lo[i];
                s1 += hi[i]; q1 += hi[i]*hi[i];
            }
            if (!vrow){ s0=q0=s1=q1=0.f; }
            st[jp*4+0]=s0; st[jp*4+1]=q0; st[jp*4+2]=s1; st[jp*4+3]=q1;
        }
    }
    if (STATS){
        __syncthreads();
        float* red = patch;
        #pragma unroll
        for (int t=0;t<16;t++){
            float v = st[t];
            #pragma unroll
            for (int o=16;o;o>>=1) v += __shfl_xor_sync(0xffffffffu, v, o);
            st[t] = v;
        }
        int wid = tid >> 5, lane = tid & 31;
        if (lane == 0){
            #pragma unroll
            for (int t=0;t<16;t++) red[wid*16 + t] = st[t];
        }
        __syncthreads();
        if (tid < 16){
            float rs = 0.f;
            #pragma unroll
            for (int wdx=0; wdx<8; wdx++) rs += red[wdx*16 + tid];
            int jp = tid >> 2;
            int sub = tid & 3;
            int ch = oc0 + 2*jp + (sub>>1);
            int tile = blockIdx.y*16 + blockIdx.x;
            g_part[((size_t)(bb*16 + ch)*256 + tile)*2 + (sub&1)] = rs;
        }
    }
}

// ---------------- norm finalize ----------------
__global__ void k_nrm(const int* __restrict__ valid_len,
                      const float* __restrict__ gamma, const float* __restrict__ beta)
{
    __shared__ float ss[256], qq[256];
    int bc = blockIdx.x;
    int i = threadIdx.x;
    ss[i] = g_part[((size_t)bc*256 + i)*2];
    qq[i] = g_part[((size_t)bc*256 + i)*2 + 1];
    __syncthreads();
    for (int o = 128; o; o >>= 1){
        if (i < o){ ss[i] += ss[i+o]; qq[i] += qq[i+o]; }
        __syncthreads();
    }
    if (i == 0){
        int b = bc >> 4, c = bc & 15;
        float cnt = (float)valid_len[b] * (float)NSEQ;
        float mean = ss[0] / cnt;
        float var = fmaxf(qq[0] / cnt - mean*mean, 0.f);
        float scale = gamma[c] * rsqrtf(var + EPSF);
        g_nrm[bc*2]     = scale;
        g_nrm[bc*2 + 1] = beta[c] - mean*scale;
    }
}

// ---------------- softmax row stats: (max, 1/sum) per row ----------------
__global__ void k_sstat(const int* __restrict__ valid_len)
{
    int warp = threadIdx.x >> 5, lane = threadIdx.x & 31;
    int row = blockIdx.x*8 + warp;
    int b = row >> 12;
    int valid = valid_len[b];
    const float* p = g_maps + (size_t)row*NSEQ;
    float v[16]; float mx = -1e30f;
    #pragma unroll
    for (int j=0;j<16;j++){
        int m = lane + 32*j;
        float x = (m < valid) ? p[m] : -1e30f;
        v[j] = x; mx = fmaxf(mx, x);
    }
    #pragma unroll
    for (int o=16;o;o>>=1) mx = fmaxf(mx, __shfl_xor_sync(0xffffffffu, mx, o));
    float s = 0.f;
    #pragma unroll
    for (int j=0;j<16;j++){
        int m = lane + 32*j;
        if (m < valid) s += __expf(v[j]-mx);
    }
    #pragma unroll
    for (int o=16;o;o>>=1) s += __shfl_xor_sync(0xffffffffu, s, o);
    if (lane == 0) g_sstat[row] = make_float2(mx, 1.f/s);
}

// ---------------- attn @ V -> ctx (exp fused in fill, K truncated at valid) ----------------
// grid (1, 8, 64), block (16,16)
__global__ void k_av(const int* __restrict__ valid_len)
{
    __shared__ __align__(16) float As[32][68];
    __shared__ __align__(16) float Bs[32][68];
    __shared__ float2 sst[64];
    int bh = blockIdx.z;
    const float* ab = g_maps + (size_t)bh*NSEQ*NSEQ;
    const float* vb = g_v    + (size_t)bh*NSEQ*DHD;
    int n0 = blockIdx.y*64;
    int tx = threadIdx.x, ty = threadIdx.y;
    int tid = ty*16 + tx;
    int kk = tid & 31, mseg = tid >> 5;
    int dd = tid & 63, kb = tid >> 6;
    int b = bh >> 3;
    int valid = valid_len[b];
    int kmax = (valid + 31) & ~31;
    if (tid < 64) sst[tid] = g_sstat[(size_t)bh*NSEQ + n0 + tid];
    __syncthreads();
    ull acc[4][2];
    #pragma unroll
    for (int i=0;i<4;i++){ acc[i][0]=0ull; acc[i][1]=0ull; }
    float pa[8], pb[8];
    #pragma unroll
    for (int i=0;i<8;i++) pa[i] = ab[(size_t)(n0 + mseg + 8*i)*NSEQ + kk];
    #pragma unroll
    for (int j=0;j<8;j++) pb[j] = vb[(size_t)(kb*8 + j)*DHD + dd];
    for (int k0 = 0; k0 < kmax; k0 += 32){
        int kg = k0 + kk;
        #pragma unroll
        for (int i=0;i<8;i++){
            int rrow = mseg + 8*i;
            float2 s = sst[rrow];
            As[kk][rrow] = (kg < valid) ? __expf(pa[i] - s.x) * s.y : 0.f;
        }
        #pragma unroll
        for (int j=0;j<8;j++) Bs[kb*8+j][dd] = pb[j];
        __syncthreads();
        if (k0 + 32 < kmax){
            #pragma unroll
            for (int i=0;i<8;i++) pa[i] = ab[(size_t)(n0 + mseg + 8*i)*NSEQ + k0 + 32 + kk];
            #pragma unroll
            for (int j=0;j<8;j++) pb[j] = vb[(size_t)(k0 + 32 + kb*8 + j)*DHD + dd];
        }
        #pragma unroll
        for (int k2=0; k2<32; k2++){
            float4 a = *(const float4*)&As[k2][ty*4];
            ulonglong2 bv2 = *(const ulonglong2*)&Bs[k2][tx*4];
            ull aa[4] = {pk2(a.x,a.x), pk2(a.y,a.y), pk2(a.z,a.z), pk2(a.w,a.w)};
            #pragma unroll
            for (int i=0;i<4;i++){ fma2(acc[i][0], aa[i], bv2.x); fma2(acc[i][1], aa[i], bv2.y); }
        }
        __syncthreads();
    }
    int h = bh & 7;
    #pragma unroll
    for (int i=0;i<4;i++){
        int n = n0 + ty*4 + i;
        float v[4]; upk2(acc[i][0], v[0], v[1]); upk2(acc[i][1], v[2], v[3]);
        #pragma unroll
        for (int j=0;j<4;j++){
            int d = h*64 + tx*4 + j;
            g_ctx[((size_t)(b*NSEQ + n))*DMODEL + d] = v[j];
        }
    }
}

// ---------------- out = ctx @ Wh + bh + query, 64x64 tile, K-slab 32 ----------------
__global__ void k_out(const float* __restrict__ Wh, const float* __restrict__ bhv,
                      const float* __restrict__ query)
{
    __shared__ __align__(16) float As[32][68];
    __shared__ __align__(16) float Bs[32][68];
    int m0 = blockIdx.y*64, n0 = blockIdx.x*64;
    int tx = threadIdx.x, ty = threadIdx.y;
    int tid = ty*16 + tx;
    int kk = tid & 31, mseg = tid >> 5;
    int nn = tid & 63, kb = tid >> 6;
    ull acc[4][2];
    #pragma unroll
    for (int i=0;i<4;i++){ acc[i][0]=0ull; acc[i][1]=0ull; }
    float pa[8], pb[8];
    #pragma unroll
    for (int i=0;i<8;i++) pa[i] = g_ctx[(size_t)(m0 + mseg + 8*i)*DMODEL + kk];
    #pragma unroll
    for (int j=0;j<8;j++) pb[j] = Wh[(size_t)(kb*8 + j)*DMODEL + n0 + nn];
    for (int k0 = 0; k0 < DMODEL; k0 += 32){
        #pragma unroll
        for (int i=0;i<8;i++) As[kk][mseg + 8*i] = pa[i];
        #pragma unroll
        for (int j=0;j<8;j++) Bs[kb*8+j][nn] = pb[j];
        __syncthreads();
        if (k0 + 32 < DMODEL){
            #pragma unroll
            for (int i=0;i<8;i++) pa[i] = g_ctx[(size_t)(m0 + mseg + 8*i)*DMODEL + k0 + 32 + kk];
            #pragma unroll
            for (int j=0;j<8;j++) pb[j] = Wh[(size_t)(k0 + 32 + kb*8 + j)*DMODEL + n0 + nn];
        }
        #pragma unroll
        for (int k2=0; k2<32; k2++){
            float4 a = *(const float4*)&As[k2][ty*4];
            ulonglong2 b = *(const ulonglong2*)&Bs[k2][tx*4];
            ull aa[4] = {pk2(a.x,a.x), pk2(a.y,a.y), pk2(a.z,a.z), pk2(a.w,a.w)};
            #pragma unroll
            for (int i=0;i<4;i++){ fma2(acc[i][0], aa[i], b.x); fma2(acc[i][1], aa[i], b.y); }
        }
        __syncthreads();
    }
    #pragma unroll
    for (int i=0;i<4;i++){
        int row = m0 + ty*4 + i;
        float v[4]; upk2(acc[i][0], v[0], v[1]); upk2(acc[i][1], v[2], v[3]);
        #pragma unroll
        for (int j=0;j<4;j++){
            int c = n0 + tx*4 + j;
            g_tmp[(size_t)row*DMODEL + c] = v[j] + bhv[c] + query[(size_t)row*DMODEL + c];
        }
    }
}

// ---------------- final layernorm ----------------
__global__ void k_ln(const float* __restrict__ gamma, const float* __restrict__ beta,
                     float* __restrict__ out)
{
    int warp = threadIdx.x >> 5, lane = threadIdx.x & 31;
    int row = blockIdx.x*8 + warp;
    const float* p = g_tmp + (size_t)row*DMODEL;
    float v[16]; float s = 0.f;
    #pragma unroll
    for (int j=0;j<16;j++){ v[j] = p[lane + 32*j]; s += v[j]; }
    #pragma unroll
    for (int o=16;o;o>>=1) s += __shfl_xor_sync(0xffffffffu, s, o);
    float mean = s * (1.f/512.f);
    float q = 0.f;
    #pragma unroll
    for (int j=0;j<16;j++){ float d = v[j]-mean; q += d*d; }
    #pragma unroll
    for (int o=16;o;o>>=1) q += __shfl_xor_sync(0xffffffffu, q, o);
    float rstd = rsqrtf(q * (1.f/512.f) + EPSF);
    #pragma unroll
    for (int j=0;j<16;j++){
        int c = lane + 32*j;
        out[(size_t)row*DMODEL + c] = gamma[c]*(v[j]-mean)*rstd + beta[c];
    }
}

// ---------------- launch ----------------
extern "C" void kernel_launch(void* const* d_in, const int* in_sizes, int n_in,
                              void* d_out, int out_size)
{
    const float* query   = (const float*)d_in[0];
    const int*   valid   = (const int*)  d_in[1];
    const float* Wq      = (const float*)d_in[2];
    const float* bq      = (const float*)d_in[3];
    const float* Wk      = (const float*)d_in[4];
    const float* bk      = (const float*)d_in[5];
    const float* Wv      = (const float*)d_in[6];
    const float* bv      = (const float*)d_in[7];
    const float* Wh      = (const float*)d_in[8];
    const float* bhv     = (const float*)d_in[9];
    const float* pos_k   = (const float*)d_in[10];
    const float* conv1_w = (const float*)d_in[11];
    const float* conv1_b = (const float*)d_in[12];
    const float* n1g     = (const float*)d_in[13];
    const float* n1b     = (const float*)d_in[14];
    const float* conv2_w = (const float*)d_in[15];
    const float* conv2_b = (const float*)d_in[16];
    const float* lng     = (const float*)d_in[17];
    const float* lnb     = (const float*)d_in[18];
    float* outp = (float*)d_out;

    dim3 t16(16,16);
    k_qkv   <<<dim3(8,64,3),  t16>>>(query, Wq,bq, Wk,bk, Wv,bv);
    k_qp    <<<dim3(512,1,1), t16>>>(pos_k);
    k_scores<<<dim3(8,8,64),  t16>>>();
    k_conv<8,2,16,false,true><<<dim3(16,16,16), 256>>>(conv1_w, conv1_b, valid);
    k_nrm   <<<128, 256>>>(valid, n1g, n1b);
    k_conv<16,1,8,true,false><<<dim3(16,16,8), 256>>>(conv2_w, conv2_b, valid);
    k_sstat <<<4096, 256>>>(valid);
    k_av    <<<dim3(1,8,64),  t16>>>(valid);
    k_out   <<<dim3(8,64),    t16>>>(Wh, bhv, query);
    k_ln    <<<512, 256>>>(lng, lnb, outp);
}

// round 17
// speedup vs baseline: 1.3845x; 1.0728x over previous
#include <cuda_runtime.h>
#include <math.h>

#define BB   8
#define NSEQ 512
#define DMODEL 512
#define HH   8
#define DHD  64
#define NPOS 121
#define EPSF 1e-7f

typedef unsigned long long ull;

// ---------------- scratch ----------------
__device__ float g_q [BB*HH*NSEQ*DHD];
__device__ float g_k [BB*HH*NSEQ*DHD];
__device__ float g_v [BB*HH*NSEQ*DHD];
__device__ float g_qp[BB*HH*NSEQ*128];
__device__ float g_maps[(size_t)BB*HH*NSEQ*NSEQ];
__device__ float g_y1  [(size_t)BB*16*NSEQ*NSEQ];
__device__ float g_part[128*256*2];
__device__ float g_nrm [128*2];
__device__ float2 g_sstat[BB*HH*NSEQ];            // per-row (max, 1/sum)
__device__ float g_ctx [BB*NSEQ*DMODEL];
__device__ float g_tmp [BB*NSEQ*DMODEL];

// ---------------- f32x2 helpers ----------------
__device__ __forceinline__ ull pk2(float a, float b){
    ull r; asm("mov.b64 %0, {%1,%2};" : "=l"(r) : "f"(a), "f"(b)); return r;
}
__device__ __forceinline__ void upk2(ull v, float& a, float& b){
    asm("mov.b64 {%0,%1}, %2;" : "=f"(a), "=f"(b) : "l"(v));
}
__device__ __forceinline__ void fma2(ull& d, ull a, ull b){
    asm("fma.rn.f32x2 %0, %1, %2, %3;" : "=l"(d) : "l"(a), "l"(b), "l"(d));
}

// ---------------- K1: QKV, 64x64 tile, K-slab 32, reg double-buffered ----------------
// grid (8, 64, 3), block (16,16)
__global__ void k_qkv(const float* __restrict__ A,
                      const float* __restrict__ Wq, const float* __restrict__ bq,
                      const float* __restrict__ Wk, const float* __restrict__ bk,
                      const float* __restrict__ Wv, const float* __restrict__ bv)
{
    __shared__ __align__(16) float As[32][68];
    __shared__ __align__(16) float Bs[32][68];
    int which = blockIdx.z;
    const float* W    = (which==0)?Wq:((which==1)?Wk:Wv);
    const float* bias = (which==0)?bq:((which==1)?bk:bv);
    float* C          = (which==0)?g_q:((which==1)?g_k:g_v);
    int m0 = blockIdx.y*64, n0 = blockIdx.x*64;
    int tx = threadIdx.x, ty = threadIdx.y;
    int tid = ty*16 + tx;
    int kk = tid & 31, mseg = tid >> 5;
    int nn = tid & 63, kb = tid >> 6;
    ull acc[4][2];
    #pragma unroll
    for (int i=0;i<4;i++){ acc[i][0]=0ull; acc[i][1]=0ull; }
    float pa[8], pb[8];
    #pragma unroll
    for (int i=0;i<8;i++) pa[i] = A[(size_t)(m0 + mseg + 8*i)*DMODEL + kk];
    #pragma unroll
    for (int j=0;j<8;j++) pb[j] = W[(size_t)(kb*8 + j)*DMODEL + n0 + nn];
    for (int k0 = 0; k0 < DMODEL; k0 += 32) {
        #pragma unroll
        for (int i=0;i<8;i++) As[kk][mseg + 8*i] = pa[i];
        #pragma unroll
        for (int j=0;j<8;j++) Bs[kb*8+j][nn] = pb[j];
        __syncthreads();
        if (k0 + 32 < DMODEL){
            #pragma unroll
            for (int i=0;i<8;i++) pa[i] = A[(size_t)(m0 + mseg + 8*i)*DMODEL + k0 + 32 + kk];
            #pragma unroll
            for (int j=0;j<8;j++) pb[j] = W[(size_t)(k0 + 32 + kb*8 + j)*DMODEL + n0 + nn];
        }
        #pragma unroll
        for (int k2=0; k2<32; k2++) {
            float4 a = *(const float4*)&As[k2][ty*4];
            ulonglong2 b = *(const ulonglong2*)&Bs[k2][tx*4];
            ull aa[4] = {pk2(a.x,a.x), pk2(a.y,a.y), pk2(a.z,a.z), pk2(a.w,a.w)};
            #pragma unroll
            for (int i=0;i<4;i++){ fma2(acc[i][0], aa[i], b.x); fma2(acc[i][1], aa[i], b.y); }
        }
        __syncthreads();
    }
    #pragma unroll
    for (int i=0;i<4;i++){
        int row = m0 + ty*4 + i;
        int bidx = row >> 9, nidx = row & 511;
        float v[4]; upk2(acc[i][0], v[0], v[1]); upk2(acc[i][1], v[2], v[3]);
        #pragma unroll
        for (int j=0;j<4;j++){
            int c = n0 + tx*4 + j;
            int h = c >> 6, dh = c & 63;
            C[(((size_t)(bidx*HH + h))*NSEQ + nidx)*DHD + dh] = v[j] + bias[c];
        }
    }
}

// ---------------- K2: qp ----------------
__global__ void k_qp(const float* __restrict__ posk)
{
    __shared__ __align__(16) float As[16][68];
    __shared__ __align__(16) float Bs[16][132];
    int m0 = blockIdx.x * 64;
    int tx = threadIdx.x, ty = threadIdx.y;
    int tid = ty*16 + tx;
    int kk = tid & 15, mrow = tid >> 4;
    int r = tid & 127, kh = tid >> 7;
    ull acc[4][4];
    #pragma unroll
    for (int i=0;i<4;i++){ acc[i][0]=0ull; acc[i][1]=0ull; acc[i][2]=0ull; acc[i][3]=0ull; }
    float pa[4], pb[8];
    #pragma unroll
    for (int i=0;i<4;i++) pa[i] = g_q[(size_t)(m0 + mrow + 16*i)*64 + kk];
    #pragma unroll
    for (int j=0;j<8;j++) pb[j] = (r < NPOS) ? posk[r*64 + kh*8 + j] : 0.f;
    for (int k0 = 0; k0 < 64; k0 += 16) {
        #pragma unroll
        for (int i=0;i<4;i++) As[kk][mrow + 16*i] = pa[i];
        #pragma unroll
        for (int j=0;j<8;j++) Bs[kh*8+j][r] = pb[j];
        __syncthreads();
        if (k0 + 16 < 64){
            #pragma unroll
            for (int i=0;i<4;i++) pa[i] = g_q[(size_t)(m0 + mrow + 16*i)*64 + k0 + 16 + kk];
            #pragma unroll
            for (int j=0;j<8;j++) pb[j] = (r < NPOS) ? posk[r*64 + k0 + 16 + kh*8 + j] : 0.f;
        }
        #pragma unroll
        for (int k2=0; k2<16; k2++){
            float4 a  = *(const float4*)&As[k2][ty*4];
            ulonglong2 b0 = *(const ulonglong2*)&Bs[k2][tx*8];
            ulonglong2 b1 = *(const ulonglong2*)&Bs[k2][tx*8+4];
            ull aa[4] = {pk2(a.x,a.x), pk2(a.y,a.y), pk2(a.z,a.z), pk2(a.w,a.w)};
            #pragma unroll
            for (int i=0;i<4;i++){
                fma2(acc[i][0], aa[i], b0.x); fma2(acc[i][1], aa[i], b0.y);
                fma2(acc[i][2], aa[i], b1.x); fma2(acc[i][3], aa[i], b1.y);
            }
        }
        __syncthreads();
    }
    #pragma unroll
    for (int i=0;i<4;i++){
        int row = m0 + ty*4 + i;
        float v[8];
        #pragma unroll
        for (int j=0;j<4;j++) upk2(acc[i][j], v[2*j], v[2*j+1]);
        #pragma unroll
        for (int j=0;j<8;j++){
            int c = tx*8 + j;
            if (c < NPOS) g_qp[(size_t)row*128 + c] = v[j];
        }
    }
}

// ---------------- K3: scores, 64x64 tile, K-slab 32 ----------------
__global__ void k_scores()
{
    __shared__ __align__(16) float As[32][68];
    __shared__ __align__(16) float Bs[32][68];
    int bh = blockIdx.z;
    const float* qb  = g_q  + (size_t)bh*NSEQ*DHD;
    const float* kb_ = g_k  + (size_t)bh*NSEQ*DHD;
    const float* qpb = g_qp + (size_t)bh*NSEQ*128;
    float* outb = g_maps + (size_t)bh*NSEQ*NSEQ;
    int n0 = blockIdx.y*64, m0 = blockIdx.x*64;
    int tx = threadIdx.x, ty = threadIdx.y;
    int tid = ty*16 + tx;
    int kk = tid & 31, mseg = tid >> 5;
    ull acc[4][2];
    #pragma unroll
    for (int i=0;i<4;i++){ acc[i][0]=0ull; acc[i][1]=0ull; }
    float pa[8], pb[8];
    #pragma unroll
    for (int i=0;i<8;i++) pa[i] = qb [(size_t)(n0 + mseg + 8*i)*DHD + kk];
    #pragma unroll
    for (int i=0;i<8;i++) pb[i] = kb_[(size_t)(m0 + mseg + 8*i)*DHD + kk];
    for (int k0 = 0; k0 < DHD; k0 += 32) {
        #pragma unroll
        for (int i=0;i<8;i++) As[kk][mseg + 8*i] = pa[i];
        #pragma unroll
        for (int i=0;i<8;i++) Bs[kk][mseg + 8*i] = pb[i];
        __syncthreads();
        if (k0 + 32 < DHD){
            #pragma unroll
            for (int i=0;i<8;i++) pa[i] = qb [(size_t)(n0 + mseg + 8*i)*DHD + k0 + 32 + kk];
            #pragma unroll
            for (int i=0;i<8;i++) pb[i] = kb_[(size_t)(m0 + mseg + 8*i)*DHD + k0 + 32 + kk];
        }
        #pragma unroll
        for (int k2=0; k2<32; k2++){
            float4 a = *(const float4*)&As[k2][ty*4];
            ulonglong2 b = *(const ulonglong2*)&Bs[k2][tx*4];
            ull aa[4] = {pk2(a.x,a.x), pk2(a.y,a.y), pk2(a.z,a.z), pk2(a.w,a.w)};
            #pragma unroll
            for (int i=0;i<4;i++){ fma2(acc[i][0], aa[i], b.x); fma2(acc[i][1], aa[i], b.y); }
        }
        __syncthreads();
    }
    #pragma unroll
    for (int i=0;i<4;i++){
        int n = n0 + ty*4 + i;
        float v[4]; upk2(acc[i][0], v[0], v[1]); upk2(acc[i][1], v[2], v[3]);
        #pragma unroll
        for (int j=0;j<4;j++){
            int m = m0 + tx*4 + j;
            int rel = m - n;
            rel = min(60, max(-60, rel)) + 60;
            outb[(size_t)n*NSEQ + m] = (v[j] + qpb[(size_t)n*128 + rel]) * 0.125f;
        }
    }
}

// ---------------- conv 5x5 (R11/R14 exact; conv2 skips tiles beyond valid) ----------------
template<int IC, int OCBLKS, int OCTOT, bool ACT, bool STATS>
__global__ void __launch_bounds__(256,4) k_conv(const float* __restrict__ w, const float* __restrict__ bias,
                                                const int* __restrict__ valid_len)
{
    __shared__ __align__(16) float patch[36*40];
    __shared__ ull ws[25*IC*4];
    __shared__ float sc[IC], sh[IC];
    const float* in = ACT ? g_y1 : g_maps;
    float* out      = ACT ? g_maps : g_y1;
    int z   = blockIdx.z;
    int bb  = z / OCBLKS;
    int oc0 = (z % OCBLKS) * 8;
    int x0 = blockIdx.x*32, y0 = blockIdx.y*32;
    // conv2 output at columns >= valid is never consumed (softmax stats and
    // attn@V both truncate at valid) — skip those tiles entirely.
    if (ACT && x0 >= valid_len[bb]) return;
    int tid = threadIdx.x;
    int tx = tid & 7, ty = tid >> 3;
    for (int idx = tid; idx < 25*IC*4; idx += 256){
        int jp = idx & 3; int rest = idx >> 2;
        int ic = rest % IC; int t = rest / IC;
        const float* wp = w + ((size_t)(t*IC + ic))*OCTOT + oc0 + 2*jp;
        ws[idx] = pk2(wp[0], wp[1]);
    }
    if (ACT && tid < IC){
        sc[tid] = g_nrm[(bb*IC + tid)*2];
        sh[tid] = g_nrm[(bb*IC + tid)*2 + 1];
    }
    ull acc[4][4];
    #pragma unroll
    for (int i=0;i<4;i++)
        #pragma unroll
        for (int jp=0;jp<4;jp++) acc[i][jp] = pk2(bias[oc0+2*jp], bias[oc0+2*jp+1]);

    float pre[6];
    {
        const float* ip = in + ((size_t)(bb*IC))*NSEQ*NSEQ;
        #pragma unroll
        for (int it=0; it<6; it++){
            int idx = tid + 256*it;
            float v = 0.f;
            if (idx < 1296){
                int rrw = idx / 36, cc = idx - rrw*36;
                int gy = y0 - 2 + rrw, gx = x0 - 2 + cc;
                if ((unsigned)gy < NSEQ && (unsigned)gx < NSEQ) v = ip[(size_t)gy*NSEQ + gx];
            }
            pre[it] = v;
        }
    }
    for (int ic = 0; ic < IC; ic++){
        __syncthreads();
        {
            float scv = ACT ? sc[ic] : 0.f;
            float shv = ACT ? sh[ic] : 0.f;
            #pragma unroll
            for (int it=0; it<6; it++){
                int idx = tid + 256*it;
                if (idx < 1296){
                    int rrw = idx / 36, cc = idx - rrw*36;
                    float v = pre[it];
                    if (ACT){
                        int gy = y0 - 2 + rrw, gx = x0 - 2 + cc;
                        v = ((unsigned)gy < NSEQ && (unsigned)gx < NSEQ)
                            ? fmaxf(fmaf(v, scv, shv), 0.f) : 0.f;
                    }
                    patch[rrw*40 + cc] = v;
                }
            }
        }
        __syncthreads();
        if (ic + 1 < IC){
            const float* ip = in + ((size_t)(bb*IC + ic + 1))*NSEQ*NSEQ;
            #pragma unroll
            for (int it=0; it<6; it++){
                int idx = tid + 256*it;
                float v = 0.f;
                if (idx < 1296){
                    int rrw = idx / 36, cc = idx - rrw*36;
                    int gy = y0 - 2 + rrw, gx = x0 - 2 + cc;
                    if ((unsigned)gy < NSEQ && (unsigned)gx < NSEQ) v = ip[(size_t)gy*NSEQ + gx];
                }
                pre[it] = v;
            }
        }
        #pragma unroll
        for (int ky=0; ky<5; ky++){
            const float4* pr = (const float4*)&patch[(ty+ky)*40 + tx*4];
            float pf[8];
            *(float4*)&pf[0] = pr[0];
            *(float4*)&pf[4] = pr[1];
            #pragma unroll
            for (int kx=0; kx<5; kx++){
                const ull* wp = &ws[((ky*5+kx)*IC + ic)*4];
                ull w0 = wp[0], w1 = wp[1], w2 = wp[2], w3 = wp[3];
                #pragma unroll
                for (int i=0;i<4;i++){
                    ull pv = pk2(pf[i+kx], pf[i+kx]);
                    fma2(acc[i][0], pv, w0);
                    fma2(acc[i][1], pv, w1);
                    fma2(acc[i][2], pv, w2);
                    fma2(acc[i][3], pv, w3);
                }
            }
        }
    }
    int y = y0 + ty;
    float st[16];
    bool vrow = STATS ? (y < valid_len[bb]) : false;
    #pragma unroll
    for (int jp=0;jp<4;jp++){
        float lo[4], hi[4];
        #pragma unroll
        for (int i=0;i<4;i++) upk2(acc[i][jp], lo[i], hi[i]);
        float4 vlo = {lo[0],lo[1],lo[2],lo[3]};
        float4 vhi = {hi[0],hi[1],hi[2],hi[3]};
        *(float4*)&out[(((size_t)(bb*OCTOT + oc0 + 2*jp    ))*NSEQ + y)*NSEQ + x0 + tx*4] = vlo;
        *(float4*)&out[(((size_t)(bb*OCTOT + oc0 + 2*jp + 1))*NSEQ + y)*NSEQ + x0 + tx*4] = vhi;
        if (STATS){
            float s0=0.f,q0=0.f,s1=0.f,q1=0.f;
            #pragma unroll
            for (int i=0;i<4;i++){
                s0 += lo[i]; q0 += lo[i]*lo[i];
                s1 += hi[i]; q1 += hi[i]*hi[i];
            }
            if (!vrow){ s0=q0=s1=q1=0.f; }
            st[jp*4+0]=s0; st[jp*4+1]=q0; st[jp*4+2]=s1; st[jp*4+3]=q1;
        }
    }
    if (STATS){
        __syncthreads();
        float* red = patch;
        #pragma unroll
        for (int t=0;t<16;t++){
            float v = st[t];
            #pragma unroll
            for (int o=16;o;o>>=1) v += __shfl_xor_sync(0xffffffffu, v, o);
            st[t] = v;
        }
        int wid = tid >> 5, lane = tid & 31;
        if (lane == 0){
            #pragma unroll
            for (int t=0;t<16;t++) red[wid*16 + t] = st[t];
        }
        __syncthreads();
        if (tid < 16){
            float rs = 0.f;
            #pragma unroll
            for (int wdx=0; wdx<8; wdx++) rs += red[wdx*16 + tid];
            int jp = tid >> 2;
            int sub = tid & 3;
            int ch = oc0 + 2*jp + (sub>>1);
            int tile = blockIdx.y*16 + blockIdx.x;
            g_part[((size_t)(bb*16 + ch)*256 + tile)*2 + (sub&1)] = rs;
        }
    }
}

// ---------------- norm finalize ----------------
__global__ void k_nrm(const int* __restrict__ valid_len,
                      const float* __restrict__ gamma, const float* __restrict__ beta)
{
    __shared__ float ss[256], qq[256];
    int bc = blockIdx.x;
    int i = threadIdx.x;
    ss[i] = g_part[((size_t)bc*256 + i)*2];
    qq[i] = g_part[((size_t)bc*256 + i)*2 + 1];
    __syncthreads();
    for (int o = 128; o; o >>= 1){
        if (i < o){ ss[i] += ss[i+o]; qq[i] += qq[i+o]; }
        __syncthreads();
    }
    if (i == 0){
        int b = bc >> 4, c = bc & 15;
        float cnt = (float)valid_len[b] * (float)NSEQ;
        float mean = ss[0] / cnt;
        float var = fmaxf(qq[0] / cnt - mean*mean, 0.f);
        float scale = gamma[c] * rsqrtf(var + EPSF);
        g_nrm[bc*2]     = scale;
        g_nrm[bc*2 + 1] = beta[c] - mean*scale;
    }
}

// ---------------- softmax row stats: (max, 1/sum) per row ----------------
__global__ void k_sstat(const int* __restrict__ valid_len)
{
    int warp = threadIdx.x >> 5, lane = threadIdx.x & 31;
    int row = blockIdx.x*8 + warp;
    int b = row >> 12;
    int valid = valid_len[b];
    const float* p = g_maps + (size_t)row*NSEQ;
    float v[16]; float mx = -1e30f;
    #pragma unroll
    for (int j=0;j<16;j++){
        int m = lane + 32*j;
        float x = (m < valid) ? p[m] : -1e30f;
        v[j] = x; mx = fmaxf(mx, x);
    }
    #pragma unroll
    for (int o=16;o;o>>=1) mx = fmaxf(mx, __shfl_xor_sync(0xffffffffu, mx, o));
    float s = 0.f;
    #pragma unroll
    for (int j=0;j<16;j++){
        int m = lane + 32*j;
        if (m < valid) s += __expf(v[j]-mx);
    }
    #pragma unroll
    for (int o=16;o;o>>=1) s += __shfl_xor_sync(0xffffffffu, s, o);
    if (lane == 0) g_sstat[row] = make_float2(mx, 1.f/s);
}

// ---------------- attn @ V -> ctx (exp fused in fill, K truncated at valid) ----------------
// grid (1, 8, 64), block (16,16)
__global__ void k_av(const int* __restrict__ valid_len)
{
    __shared__ __align__(16) float As[32][68];
    __shared__ __align__(16) float Bs[32][68];
    __shared__ float2 sst[64];
    int bh = blockIdx.z;
    const float* ab = g_maps + (size_t)bh*NSEQ*NSEQ;
    const float* vb = g_v    + (size_t)bh*NSEQ*DHD;
    int n0 = blockIdx.y*64;
    int tx = threadIdx.x, ty = threadIdx.y;
    int tid = ty*16 + tx;
    int kk = tid & 31, mseg = tid >> 5;
    int dd = tid & 63, kb = tid >> 6;
    int b = bh >> 3;
    int valid = valid_len[b];
    int kmax = (valid + 31) & ~31;
    if (tid < 64) sst[tid] = g_sstat[(size_t)bh*NSEQ + n0 + tid];
    __syncthreads();
    ull acc[4][2];
    #pragma unroll
    for (int i=0;i<4;i++){ acc[i][0]=0ull; acc[i][1]=0ull; }
    float pa[8], pb[8];
    #pragma unroll
    for (int i=0;i<8;i++) pa[i] = ab[(size_t)(n0 + mseg + 8*i)*NSEQ + kk];
    #pragma unroll
    for (int j=0;j<8;j++) pb[j] = vb[(size_t)(kb*8 + j)*DHD + dd];
    for (int k0 = 0; k0 < kmax; k0 += 32){
        int kg = k0 + kk;
        #pragma unroll
        for (int i=0;i<8;i++){
            int rrow = mseg + 8*i;
            float2 s = sst[rrow];
            As[kk][rrow] = (kg < valid) ? __expf(pa[i] - s.x) * s.y : 0.f;
        }
        #pragma unroll
        for (int j=0;j<8;j++) Bs[kb*8+j][dd] = pb[j];
        __syncthreads();
        if (k0 + 32 < kmax){
            #pragma unroll
            for (int i=0;i<8;i++) pa[i] = ab[(size_t)(n0 + mseg + 8*i)*NSEQ + k0 + 32 + kk];
            #pragma unroll
            for (int j=0;j<8;j++) pb[j] = vb[(size_t)(k0 + 32 + kb*8 + j)*DHD + dd];
        }
        #pragma unroll
        for (int k2=0; k2<32; k2++){
            float4 a = *(const float4*)&As[k2][ty*4];
            ulonglong2 bv2 = *(const ulonglong2*)&Bs[k2][tx*4];
            ull aa[4] = {pk2(a.x,a.x), pk2(a.y,a.y), pk2(a.z,a.z), pk2(a.w,a.w)};
            #pragma unroll
            for (int i=0;i<4;i++){ fma2(acc[i][0], aa[i], bv2.x); fma2(acc[i][1], aa[i], bv2.y); }
        }
        __syncthreads();
    }
    int h = bh & 7;
    #pragma unroll
    for (int i=0;i<4;i++){
        int n = n0 + ty*4 + i;
        float v[4]; upk2(acc[i][0], v[0], v[1]); upk2(acc[i][1], v[2], v[3]);
        #pragma unroll
        for (int j=0;j<4;j++){
            int d = h*64 + tx*4 + j;
            g_ctx[((size_t)(b*NSEQ + n))*DMODEL + d] = v[j];
        }
    }
}

// ---------------- out = ctx @ Wh + bh + query, 64x64 tile, K-slab 32 ----------------
__global__ void k_out(const float* __restrict__ Wh, const float* __restrict__ bhv,
                      const float* __restrict__ query)
{
    __shared__ __align__(16) float As[32][68];
    __shared__ __align__(16) float Bs[32][68];
    int m0 = blockIdx.y*64, n0 = blockIdx.x*64;
    int tx = threadIdx.x, ty = threadIdx.y;
    int tid = ty*16 + tx;
    int kk = tid & 31, mseg = tid >> 5;
    int nn = tid & 63, kb = tid >> 6;
    ull acc[4][2];
    #pragma unroll
    for (int i=0;i<4;i++){ acc[i][0]=0ull; acc[i][1]=0ull; }
    float pa[8], pb[8];
    #pragma unroll
    for (int i=0;i<8;i++) pa[i] = g_ctx[(size_t)(m0 + mseg + 8*i)*DMODEL + kk];
    #pragma unroll
    for (int j=0;j<8;j++) pb[j] = Wh[(size_t)(kb*8 + j)*DMODEL + n0 + nn];
    for (int k0 = 0; k0 < DMODEL; k0 += 32){
        #pragma unroll
        for (int i=0;i<8;i++) As[kk][mseg + 8*i] = pa[i];
        #pragma unroll
        for (int j=0;j<8;j++) Bs[kb*8+j][nn] = pb[j];
        __syncthreads();
        if (k0 + 32 < DMODEL){
            #pragma unroll
            for (int i=0;i<8;i++) pa[i] = g_ctx[(size_t)(m0 + mseg + 8*i)*DMODEL + k0 + 32 + kk];
            #pragma unroll
            for (int j=0;j<8;j++) pb[j] = Wh[(size_t)(k0 + 32 + kb*8 + j)*DMODEL + n0 + nn];
        }
        #pragma unroll
        for (int k2=0; k2<32; k2++){
            float4 a = *(const float4*)&As[k2][ty*4];
            ulonglong2 b = *(const ulonglong2*)&Bs[k2][tx*4];
            ull aa[4] = {pk2(a.x,a.x), pk2(a.y,a.y), pk2(a.z,a.z), pk2(a.w,a.w)};
            #pragma unroll
            for (int i=0;i<4;i++){ fma2(acc[i][0], aa[i], b.x); fma2(acc[i][1], aa[i], b.y); }
        }
        __syncthreads();
    }
    #pragma unroll
    for (int i=0;i<4;i++){
        int row = m0 + ty*4 + i;
        float v[4]; upk2(acc[i][0], v[0], v[1]); upk2(acc[i][1], v[2], v[3]);
        #pragma unroll
        for (int j=0;j<4;j++){
            int c = n0 + tx*4 + j;
            g_tmp[(size_t)row*DMODEL + c] = v[j] + bhv[c] + query[(size_t)row*DMODEL + c];
        }
    }
}

// ---------------- final layernorm ----------------
__global__ void k_ln(const float* __restrict__ gamma, const float* __restrict__ beta,
                     float* __restrict__ out)
{
    int warp = threadIdx.x >> 5, lane = threadIdx.x & 31;
    int row = blockIdx.x*8 + warp;
    const float* p = g_tmp + (size_t)row*DMODEL;
    float v[16]; float s = 0.f;
    #pragma unroll
    for (int j=0;j<16;j++){ v[j] = p[lane + 32*j]; s += v[j]; }
    #pragma unroll
    for (int o=16;o;o>>=1) s += __shfl_xor_sync(0xffffffffu, s, o);
    float mean = s * (1.f/512.f);
    float q = 0.f;
    #pragma unroll
    for (int j=0;j<16;j++){ float d = v[j]-mean; q += d*d; }
    #pragma unroll
    for (int o=16;o;o>>=1) q += __shfl_xor_sync(0xffffffffu, q, o);
    float rstd = rsqrtf(q * (1.f/512.f) + EPSF);
    #pragma unroll
    for (int j=0;j<16;j++){
        int c = lane + 32*j;
        out[(size_t)row*DMODEL + c] = gamma[c]*(v[j]-mean)*rstd + beta[c];
    }
}

// ---------------- launch ----------------
extern "C" void kernel_launch(void* const* d_in, const int* in_sizes, int n_in,
                              void* d_out, int out_size)
{
    const float* query   = (const float*)d_in[0];
    const int*   valid   = (const int*)  d_in[1];
    const float* Wq      = (const float*)d_in[2];
    const float* bq      = (const float*)d_in[3];
    const float* Wk      = (const float*)d_in[4];
    const float* bk      = (const float*)d_in[5];
    const float* Wv      = (const float*)d_in[6];
    const float* bv      = (const float*)d_in[7];
    const float* Wh      = (const float*)d_in[8];
    const float* bhv     = (const float*)d_in[9];
    const float* pos_k   = (const float*)d_in[10];
    const float* conv1_w = (const float*)d_in[11];
    const float* conv1_b = (const float*)d_in[12];
    const float* n1g     = (const float*)d_in[13];
    const float* n1b     = (const float*)d_in[14];
    const float* conv2_w = (const float*)d_in[15];
    const float* conv2_b = (const float*)d_in[16];
    const float* lng     = (const float*)d_in[17];
    const float* lnb     = (const float*)d_in[18];
    float* outp = (float*)d_out;

    dim3 t16(16,16);
    k_qkv   <<<dim3(8,64,3),  t16>>>(query, Wq,bq, Wk,bk, Wv,bv);
    k_qp    <<<dim3(512,1,1), t16>>>(pos_k);
    k_scores<<<dim3(8,8,64),  t16>>>();
    k_conv<8,2,16,false,true><<<dim3(16,16,16), 256>>>(conv1_w, conv1_b, valid);
    k_nrm   <<<128, 256>>>(valid, n1g, n1b);
    k_conv<16,1,8,true,false><<<dim3(16,16,8), 256>>>(conv2_w, conv2_b, valid);
    k_sstat <<<4096, 256>>>(valid);
    k_av    <<<dim3(1,8,64),  t16>>>(valid);
    k_out   <<<dim3(8,64),    t16>>>(Wh, bhv, query);
    k_ln    <<<512, 256>>>(lng, lnb, outp);
}